// round 7
// baseline (speedup 1.0000x reference)
#include <cuda_runtime.h>
#include <cuda_bf16.h>
#include <math.h>

// SwitchMoE with the reference's dim-1 scatter gate bug:
//   mask[b, top1[b,n], 0] = 1  =>  output nonzero only for n<8, expert 0.
// E=8, DIM=128, HID=512, OUT=128, B=16, H=W=64, N=4096.
//
// SINGLE persistent kernel, 640 blocks x 128 threads (all co-resident):
//   phase 1: blocks <512 = gate logits/argmax + zero out (double-buffered);
//            blocks >=512 = expert-0 fc1 at the 18 needed pixels/batch.
//   grid barrier (atomic counter + epoch, self-resetting => graph-replay safe)
//   phase 2: blocks <128 = dwconv+GELU+fc2+gate for the 128 nonzero rows.

#define BATCH 16
#define NTOK  4096
#define DIM   128
#define NEXP  8
#define HID   512
#define OUTD  128
#define EPS   1e-6f
#define NBLK  640

// ---- scratch (device globals; every data element rewritten each call) ----
__device__ unsigned g_bm[512];                    // per-gate-block OR of (1<<argmax)
__device__ float    g_prob0[BATCH * NEXP];        // softmax p(expert0) at token n<8
__device__ float    g_h1[BATCH * 2 * 9 * HID];    // expert-0 fc1 at (h in {0,1}, w in [0,9))
__device__ unsigned g_count = 0;                  // barrier arrivals (reset each launch)
__device__ unsigned g_epoch = 0;                  // barrier release (monotonic)

// grid-wide barrier: valid because all NBLK blocks are simultaneously resident.
__device__ __forceinline__ void grid_barrier() {
    __syncthreads();                       // block writes happen-before thread0's fence
    if (threadIdx.x == 0) {
        __threadfence();                   // cumulative: publish block's global writes
        unsigned e = *(volatile unsigned*)&g_epoch;
        unsigned t = atomicAdd(&g_count, 1);
        if (t == NBLK - 1) {
            g_count = 0;                   // self-reset for next launch/replay
            __threadfence();
            atomicAdd(&g_epoch, 1);        // release
        } else {
            while (*(volatile unsigned*)&g_epoch == e) { __nanosleep(64); }
        }
        __threadfence();                   // acquire
    }
    __syncthreads();
}

__global__ void __launch_bounds__(128) moe_kernel(
    const float* __restrict__ x, const float* __restrict__ wg,
    const float* __restrict__ bg, const float* __restrict__ W1,
    const float* __restrict__ B1, const float* __restrict__ Wd,
    const float* __restrict__ Bd, const float* __restrict__ W2,
    const float* __restrict__ B2, float* __restrict__ out)
{
    // shared pool, aliased per path/phase:
    //   gate  : wg_s[1024] | bg_s[8] | xs[2][128*20]  = 6152 floats
    //   fc1   : xs18[18*128]                          = 2304 floats
    //   phase2: gs[512]                               =  512 floats
    __shared__ float pool[6152];
    __shared__ unsigned warpor[4];
    __shared__ unsigned mor[BATCH];

    const int tid = threadIdx.x;
    const int blk = blockIdx.x;

    // ======================= PHASE 1 =======================
    if (blk < 512) {
        // ---------------- gate path ----------------
        float* wg_s = pool;                 // [DIM*NEXP]
        float* bg_s = pool + 1024;          // [NEXP]
        float* xs0  = pool + 1032;          // [128*20]
        float* xs1  = pool + 1032 + 2560;   // [128*20]

        const int tok0 = blk * 128;
        const float* xb = x + (size_t)tok0 * DIM;

        for (int i = tid; i < DIM * NEXP; i += 128) wg_s[i] = wg[i];
        if (tid < NEXP) bg_s[tid] = bg[tid];

        // per-thread staging coords: thread stages token t, quarter q of a 16-dim chunk
        const int st_t = tid >> 2, st_q = tid & 3;   // plus 3 more tokens at +32,+64,+96

        float acc[NEXP];
#pragma unroll
        for (int e = 0; e < NEXP; e++) acc[e] = 0.0f;

        // prefetch chunk 0
        float4 r[4];
#pragma unroll
        for (int k = 0; k < 4; k++)
            r[k] = *(const float4*)(xb + (size_t)(st_t + 32 * k) * DIM + st_q * 4);

#pragma unroll
        for (int ch = 0; ch < 8; ch++) {
            float* buf = (ch & 1) ? xs1 : xs0;
#pragma unroll
            for (int k = 0; k < 4; k++)
                *(float4*)(buf + (st_t + 32 * k) * 20 + st_q * 4) = r[k];
            __syncthreads();   // buf ready; also: everyone done reading buf 2 iters ago
            if (ch < 7) {      // prefetch next chunk (overlaps with compute below)
#pragma unroll
                for (int k = 0; k < 4; k++)
                    r[k] = *(const float4*)(xb + (size_t)(st_t + 32 * k) * DIM
                                            + (ch + 1) * 16 + st_q * 4);
            }
#pragma unroll
            for (int d4 = 0; d4 < 4; d4++) {
                float4 xv = *(const float4*)(buf + tid * 20 + d4 * 4);
                float xarr[4] = {xv.x, xv.y, xv.z, xv.w};
#pragma unroll
                for (int jj = 0; jj < 4; jj++) {
                    int dd = ch * 16 + d4 * 4 + jj;
                    float4 w0 = *(const float4*)(wg_s + dd * 8);
                    float4 w1 = *(const float4*)(wg_s + dd * 8 + 4);
                    float xd = xarr[jj];
                    acc[0] += xd * w0.x; acc[1] += xd * w0.y;
                    acc[2] += xd * w0.z; acc[3] += xd * w0.w;
                    acc[4] += xd * w1.x; acc[5] += xd * w1.y;
                    acc[6] += xd * w1.z; acc[7] += xd * w1.w;
                }
            }
        }

        // logits, first-max argmax (matches jnp.argmax), softmax p0 at n<8
        float l[NEXP];
#pragma unroll
        for (int e = 0; e < NEXP; e++) l[e] = acc[e] + bg_s[e];
        float m = l[0]; int am = 0;
#pragma unroll
        for (int e = 1; e < NEXP; e++) if (l[e] > m) { m = l[e]; am = e; }

        const int tok = tok0 + tid;
        const int b = tok >> 12;
        const int n = tok & (NTOK - 1);
        if (n < NEXP) {
            float s = 0.0f;
#pragma unroll
            for (int e = 0; e < NEXP; e++) s += expf(l[e] - m);
            g_prob0[b * NEXP + n] = expf(l[0] - m) / s;
        }

        unsigned wor = __reduce_or_sync(0xffffffffu, 1u << am);
        if ((tid & 31) == 0) warpor[tid >> 5] = wor;

        // zero this block's 128 output rows (contiguous 64KB)
        float4 z = make_float4(0.f, 0.f, 0.f, 0.f);
        float* ob = out + (size_t)tok0 * OUTD;
#pragma unroll 8
        for (int i = tid; i < 128 * (OUTD / 4); i += 128)
            *(float4*)(ob + (size_t)i * 4) = z;

        __syncthreads();
        if (tid == 0)
            g_bm[blk] = warpor[0] | warpor[1] | warpor[2] | warpor[3];
    } else {
        // ---------------- fc1 path ----------------
        // expert-0 fc1 at 18 pixels/batch: h in {0,1}, w in [0,9)
        float* xs = pool;                   // [18*DIM]
        const int bb = blk - 512;           // [0,128)
        const int b  = bb >> 3, cg = bb & 7;

        for (int i = tid; i < 18 * DIM; i += 128) {
            int p = i >> 7, d = i & (DIM - 1);
            int h = p / 9, w = p % 9;
            int nn = h * 64 + w;
            xs[p * DIM + d] = x[((size_t)b * NTOK + nn) * DIM + d];
        }
        __syncthreads();

        const int c  = cg * 64 + (tid & 63);
        const int t0 = tid >> 6;            // tokens t0, t0+2, ..., t0+16

        float acc9[9];
        float bv = B1[c];
#pragma unroll
        for (int k = 0; k < 9; k++) acc9[k] = bv;

        for (int d4 = 0; d4 < DIM / 4; d4++) {
            float4 xv[9];
#pragma unroll
            for (int k = 0; k < 9; k++)
                xv[k] = *(const float4*)(xs + (t0 + 2 * k) * DIM + d4 * 4);
#pragma unroll
            for (int j = 0; j < 4; j++) {
                float w = W1[(size_t)(d4 * 4 + j) * HID + c];
#pragma unroll
                for (int k = 0; k < 9; k++) {
                    float xd = ((const float*)&xv[k])[j];
                    acc9[k] += xd * w;
                }
            }
        }

#pragma unroll
        for (int k = 0; k < 9; k++) {
            int p = t0 + 2 * k;
            int h = p / 9, w = p % 9;
            g_h1[(((size_t)b * 2 + h) * 9 + w) * HID + c] = acc9[k];
        }
    }

    // ======================= BARRIER =======================
    grid_barrier();

    // ======================= PHASE 2 =======================
    // 128 blocks: one (b, j) nonzero output row each.
    if (blk >= 128) return;
    {
        const int b = blk >> 3, j = blk & 7;
        float* gs = pool;                   // [HID] (safe: barrier passed)

        // mask[b'] bit j: OR of the 32 gate-block masks of batch b'
        if (tid < BATCH) mor[tid] = 0u;
        __syncthreads();
#pragma unroll
        for (int k = 0; k < 4; k++) {
            int i = tid + k * 128;
            atomicOr(&mor[i >> 5], g_bm[i]);
        }

        // depthwise conv + exact GELU, 4 channels/thread (coalesced)
#pragma unroll
        for (int k = 0; k < HID / 128; k++) {
            int c = tid + k * 128;
            float conv = Bd[c];
#pragma unroll
            for (int hh = 0; hh < 2; hh++) {
#pragma unroll
                for (int kw = 0; kw < 3; kw++) {
                    int wp = j + kw - 1;
                    if (wp >= 0 && wp <= 8) {
                        conv += g_h1[(((size_t)b * 2 + hh) * 9 + wp) * HID + c]
                              * Wd[((hh + 1) * 3 + kw) * HID + c];
                    }
                }
            }
            gs[c] = 0.5f * conv * (1.0f + erff(conv * 0.70710678118654752f));
        }
        __syncthreads();

        // gate scale, computed redundantly per-thread (uniform; broadcast loads)
        float s = 0.0f;
#pragma unroll
        for (int bb = 0; bb < BATCH; bb++)
            s += g_prob0[bb * NEXP + j] * (float)((mor[bb] >> j) & 1u);
        float gv = g_prob0[b * NEXP + j] * (float)((mor[b] >> j) & 1u);
        float gate_s = gv / (s + EPS) * (float)BATCH;   // capacity = 16.0

        // fc2: thread = output channel o
        const int o = tid;
        float acc = B2[o];
#pragma unroll 16
        for (int c = 0; c < HID; c++)
            acc += gs[c] * W2[(size_t)c * OUTD + o];

        out[((size_t)b * NTOK + j) * OUTD + o] = gate_s * acc;
    }
}

// ------------------------------------------------------------------
extern "C" void kernel_launch(void* const* d_in, const int* in_sizes, int n_in,
                              void* d_out, int out_size)
{
    // input order: x, [H, W,] wg, bg, W1, B1, Wd, Bd, W2, B2
    int o = (n_in >= 11) ? 3 : 1;
    const float* x  = (const float*)d_in[0];
    const float* wg = (const float*)d_in[o + 0];
    const float* bg = (const float*)d_in[o + 1];
    const float* W1 = (const float*)d_in[o + 2];
    const float* B1 = (const float*)d_in[o + 3];
    const float* Wd = (const float*)d_in[o + 4];
    const float* Bd = (const float*)d_in[o + 5];
    const float* W2 = (const float*)d_in[o + 6];
    const float* B2 = (const float*)d_in[o + 7];
    float* out = (float*)d_out;

    moe_kernel<<<NBLK, 128>>>(x, wg, bg, W1, B1, Wd, Bd, W2, B2, out);
}

// round 8
// speedup vs baseline: 1.4211x; 1.4211x over previous
#include <cuda_runtime.h>
#include <cuda_bf16.h>
#include <cuda_pipeline.h>
#include <math.h>

// SwitchMoE with the reference's dim-1 scatter gate bug:
//   mask[b, top1[b,n], 0] = 1  =>  output nonzero only for n<8, expert 0.
// E=8, DIM=128, HID=512, OUT=128, B=16, H=W=64, N=4096.
//
// 2 launches (R5 structure — the fused grid-barrier version regressed):
//   K1 (grid 640): blocks <512 = gate logits/argmax + out zeroing, with
//                  cp.async double-buffered x staging;
//                  blocks >=512 = expert-0 fc1 at the 18 needed pixels/batch.
//   K2 (grid 16x8, 512 thr): dwconv+GELU+fc2+gate, fc2 as 16 slices x 32 thr
//                  with float4 W2 loads, fully unrolled.

#define BATCH 16
#define NTOK  4096
#define DIM   128
#define NEXP  8
#define HID   512
#define OUTD  128
#define EPS   1e-6f

// ---- scratch (device globals; every element rewritten each call) ----
__device__ unsigned g_bm[512];                    // per-gate-block OR of (1<<argmax)
__device__ float    g_prob0[BATCH * NEXP];        // softmax p(expert0) at token n<8
__device__ float    g_h1[BATCH * 2 * 9 * HID];    // expert-0 fc1 at (h in {0,1}, w in [0,9))

// ------------------------------------------------------------------
// K1: fused gate (+zero out) and fc1
// ------------------------------------------------------------------
__global__ void __launch_bounds__(128) gate_fc1_kernel(
    const float* __restrict__ x, const float* __restrict__ wg,
    const float* __restrict__ bg, const float* __restrict__ W1,
    const float* __restrict__ B1, float* __restrict__ out)
{
    // shared pool, aliased per path:
    //   gate: wg_s[1024] | bg_s[8] | xs[2][128*20]  = 6152 floats
    //   fc1 : xs18[18*128]                          = 2304 floats
    __shared__ float pool[6152];
    __shared__ unsigned warpor[4];

    const int tid = threadIdx.x;
    const int blk = blockIdx.x;

    if (blk < 512) {
        // ================= gate path =================
        float* wg_s = pool;                 // [DIM*NEXP]
        float* bg_s = pool + 1024;          // [NEXP]
        float* xsbuf[2] = { pool + 1032, pool + 1032 + 2560 };  // [128*20] each

        const int tok0 = blk * 128;
        const float* xb = x + (size_t)tok0 * DIM;

        for (int i = tid; i < DIM * NEXP; i += 128) wg_s[i] = wg[i];
        if (tid < NEXP) bg_s[tid] = bg[tid];

        // staging coords: thread copies 16B for tokens st_t+32k, quarter st_q
        const int st_t = tid >> 2, st_q = tid & 3;

        // stage chunk 0 (async)
#pragma unroll
        for (int k = 0; k < 4; k++)
            __pipeline_memcpy_async(
                xsbuf[0] + (st_t + 32 * k) * 20 + st_q * 4,
                xb + (size_t)(st_t + 32 * k) * DIM + st_q * 4, 16);
        __pipeline_commit();

        float acc[NEXP];
#pragma unroll
        for (int e = 0; e < NEXP; e++) acc[e] = 0.0f;

#pragma unroll
        for (int ch = 0; ch < 8; ch++) {
            if (ch < 7) {   // stage next chunk into the other buffer
                float* nb = xsbuf[(ch + 1) & 1];
#pragma unroll
                for (int k = 0; k < 4; k++)
                    __pipeline_memcpy_async(
                        nb + (st_t + 32 * k) * 20 + st_q * 4,
                        xb + (size_t)(st_t + 32 * k) * DIM + (ch + 1) * 16 + st_q * 4, 16);
                __pipeline_commit();
                __pipeline_wait_prior(1);   // chunk ch landed
            } else {
                __pipeline_wait_prior(0);
            }
            __syncthreads();                // chunk ch visible (also wg_s on ch=0)

            const float* buf = xsbuf[ch & 1];
#pragma unroll
            for (int d4 = 0; d4 < 4; d4++) {
                float4 xv = *(const float4*)(buf + tid * 20 + d4 * 4);
                float xarr[4] = {xv.x, xv.y, xv.z, xv.w};
#pragma unroll
                for (int jj = 0; jj < 4; jj++) {
                    int dd = ch * 16 + d4 * 4 + jj;
                    float4 w0 = *(const float4*)(wg_s + dd * 8);
                    float4 w1 = *(const float4*)(wg_s + dd * 8 + 4);
                    float xd = xarr[jj];
                    acc[0] += xd * w0.x; acc[1] += xd * w0.y;
                    acc[2] += xd * w0.z; acc[3] += xd * w0.w;
                    acc[4] += xd * w1.x; acc[5] += xd * w1.y;
                    acc[6] += xd * w1.z; acc[7] += xd * w1.w;
                }
            }
            __syncthreads();                // done reading buf before it is re-filled
        }

        // logits, first-max argmax (matches jnp.argmax), softmax p0 at n<8
        float l[NEXP];
#pragma unroll
        for (int e = 0; e < NEXP; e++) l[e] = acc[e] + bg_s[e];
        float m = l[0]; int am = 0;
#pragma unroll
        for (int e = 1; e < NEXP; e++) if (l[e] > m) { m = l[e]; am = e; }

        const int tok = tok0 + tid;
        const int b = tok >> 12;
        const int n = tok & (NTOK - 1);
        if (n < NEXP) {
            float s = 0.0f;
#pragma unroll
            for (int e = 0; e < NEXP; e++) s += expf(l[e] - m);
            g_prob0[b * NEXP + n] = expf(l[0] - m) / s;
        }

        // per-block argmax bitmask (replay-safe: every slot rewritten each call)
        unsigned wor = __reduce_or_sync(0xffffffffu, 1u << am);
        if ((tid & 31) == 0) warpor[tid >> 5] = wor;

        // zero this block's 128 output rows (contiguous 64KB)
        float4 z = make_float4(0.f, 0.f, 0.f, 0.f);
        float* ob = out + (size_t)tok0 * OUTD;
#pragma unroll 8
        for (int i = tid; i < 128 * (OUTD / 4); i += 128)
            *(float4*)(ob + (size_t)i * 4) = z;

        __syncthreads();
        if (tid == 0)
            g_bm[blk] = warpor[0] | warpor[1] | warpor[2] | warpor[3];
    } else {
        // ================= fc1 path =================
        // expert-0 fc1 at 18 pixels/batch: h in {0,1}, w in [0,9)
        float* xs = pool;                   // [18*DIM]
        const int bb = blk - 512;           // [0,128)
        const int b  = bb >> 3, cg = bb & 7;

        for (int i = tid; i < 18 * DIM; i += 128) {
            int p = i >> 7, d = i & (DIM - 1);
            int h = p / 9, w = p % 9;
            int nn = h * 64 + w;
            xs[p * DIM + d] = x[((size_t)b * NTOK + nn) * DIM + d];
        }
        __syncthreads();

        const int c  = cg * 64 + (tid & 63);
        const int t0 = tid >> 6;            // tokens t0, t0+2, ..., t0+16

        float acc9[9];
        float bv = B1[c];
#pragma unroll
        for (int k = 0; k < 9; k++) acc9[k] = bv;

        for (int d4 = 0; d4 < DIM / 4; d4++) {
            float4 xv[9];
#pragma unroll
            for (int k = 0; k < 9; k++)
                xv[k] = *(const float4*)(xs + (t0 + 2 * k) * DIM + d4 * 4);
#pragma unroll
            for (int j = 0; j < 4; j++) {
                float w = W1[(size_t)(d4 * 4 + j) * HID + c];
#pragma unroll
                for (int k = 0; k < 9; k++) {
                    float xd = ((const float*)&xv[k])[j];
                    acc9[k] += xd * w;
                }
            }
        }

#pragma unroll
        for (int k = 0; k < 9; k++) {
            int p = t0 + 2 * k;
            int h = p / 9, w = p % 9;
            g_h1[(((size_t)b * 2 + h) * 9 + w) * HID + c] = acc9[k];
        }
    }
}

// ------------------------------------------------------------------
// K2: dwconv(3x3, SAME) + bias + exact GELU + fc2 + gate, 128 nonzero rows.
// grid (16,8) x 512 threads.
//   conv: 1 channel/thread (coalesced).
//   fc2 : warp w = HID slice [32w, 32w+32); thread t owns outputs 4t..4t+3
//         via float4 W2 loads; 32 fully-unrolled iterations -> deep MLP.
// ------------------------------------------------------------------
__global__ void __launch_bounds__(512) out_kernel(
    const float* __restrict__ Wd, const float* __restrict__ Bd,
    const float* __restrict__ W2, const float* __restrict__ B2,
    float* __restrict__ out)
{
    const int b = blockIdx.x, j = blockIdx.y;
    const int tid = threadIdx.x;
    __shared__ float gs[HID];
    __shared__ float partial[16 * OUTD];
    __shared__ unsigned mor[BATCH];

    // mask[b'] = OR over the 32 gate blocks of batch b' (tid = b'*32 + blk)
    {
        unsigned m = __reduce_or_sync(0xffffffffu, g_bm[tid]);
        if ((tid & 31) == 0) mor[tid >> 5] = m;
    }

    // depthwise conv at (h=0, w=j): kh in {1,2} -> h' in {0,1}; w' = j+kw-1
    {
        const int c = tid;                  // HID == 512 == blockDim
        float conv = Bd[c];
#pragma unroll
        for (int hh = 0; hh < 2; hh++) {
#pragma unroll
            for (int kw = 0; kw < 3; kw++) {
                int wp = j + kw - 1;
                if (wp >= 0 && wp <= 8) {
                    conv += g_h1[(((size_t)b * 2 + hh) * 9 + wp) * HID + c]
                          * Wd[((hh + 1) * 3 + kw) * HID + c];
                }
            }
        }
        // exact GELU: 0.5*x*(1+erf(x/sqrt(2)))
        gs[c] = 0.5f * conv * (1.0f + erff(conv * 0.70710678118654752f));
    }
    __syncthreads();   // gs + mor ready

    // gate scale, computed redundantly per-thread (uniform broadcast loads)
    float gate_s;
    {
        float s = 0.0f;
#pragma unroll
        for (int bb = 0; bb < BATCH; bb++)
            s += g_prob0[bb * NEXP + j] * (float)((mor[bb] >> j) & 1u);
        float gv = g_prob0[b * NEXP + j] * (float)((mor[b] >> j) & 1u);
        gate_s = gv / (s + EPS) * (float)BATCH;   // capacity = 16.0
    }

    // fc2 partials: warp w covers c in [32w, 32w+32); thread t -> outputs 4t..4t+3
    {
        const int s = tid >> 5, t = tid & 31;
        const float* w2p = W2 + (size_t)(s * 32) * OUTD + 4 * t;
        const float* gp  = gs + s * 32;
        float4 a = make_float4(0.f, 0.f, 0.f, 0.f);
#pragma unroll
        for (int i = 0; i < 32; i++) {
            float g = gp[i];
            float4 w = *(const float4*)(w2p + (size_t)i * OUTD);
            a.x += g * w.x; a.y += g * w.y; a.z += g * w.z; a.w += g * w.w;
        }
        *(float4*)(partial + s * OUTD + 4 * t) = a;
    }
    __syncthreads();

    // reduce 16 slices + bias + gate, store row
    if (tid < OUTD) {
        float r = B2[tid];
#pragma unroll
        for (int s = 0; s < 16; s++) r += partial[s * OUTD + tid];
        out[((size_t)b * NTOK + j) * OUTD + tid] = gate_s * r;
    }
}

// ------------------------------------------------------------------
extern "C" void kernel_launch(void* const* d_in, const int* in_sizes, int n_in,
                              void* d_out, int out_size)
{
    // input order: x, [H, W,] wg, bg, W1, B1, Wd, Bd, W2, B2
    int o = (n_in >= 11) ? 3 : 1;
    const float* x  = (const float*)d_in[0];
    const float* wg = (const float*)d_in[o + 0];
    const float* bg = (const float*)d_in[o + 1];
    const float* W1 = (const float*)d_in[o + 2];
    const float* B1 = (const float*)d_in[o + 3];
    const float* Wd = (const float*)d_in[o + 4];
    const float* Bd = (const float*)d_in[o + 5];
    const float* W2 = (const float*)d_in[o + 6];
    const float* B2 = (const float*)d_in[o + 7];
    float* out = (float*)d_out;

    gate_fc1_kernel<<<640, 128>>>(x, wg, bg, W1, B1, out);
    out_kernel<<<dim3(16, 8), 512>>>(Wd, Bd, W2, B2, out);
}

// round 9
// speedup vs baseline: 1.4448x; 1.0167x over previous
#include <cuda_runtime.h>
#include <cuda_bf16.h>
#include <cuda_pipeline.h>
#include <math.h>

// SwitchMoE with the reference's dim-1 scatter gate bug:
//   mask[b, top1[b,n], 0] = 1  =>  output nonzero only for n<8, expert 0.
// E=8, DIM=128, HID=512, OUT=128, B=16, H=W=64, N=4096.
//
// 2 launches:
//   K1 (grid 640, READ-ONLY): blocks <512 = gate logits/argmax (cp.async
//       double-buffered); blocks >=512 = expert-0 fc1 at 18 pixels/batch.
//   K2 (grid 448 x 512thr, launch_bounds(512,1)):
//       blocks <64  = dwconv+GELU+fc2+gate for 2 batches x 1 j each
//                     (writes the 128 rows with n<8, unconditionally);
//       blocks >=64 = zero all rows with n>=8 (33.4 MB of stores).

#define BATCH 16
#define NTOK  4096
#define DIM   128
#define NEXP  8
#define HID   512
#define OUTD  128
#define EPS   1e-6f

// zero-coverage: rows n in [8,4096) for each b  -> 16*4088*32 float4
#define ZROWS      4088
#define ZTOT_VEC   (BATCH * ZROWS * (OUTD / 4))   // 2,093,056
#define ZBLOCKS    384
#define ZTHREADS   (ZBLOCKS * 512)                // 196,608

// ---- scratch (device globals; every element rewritten each call) ----
__device__ unsigned g_bm[512];                    // per-gate-block OR of (1<<argmax)
__device__ float    g_prob0[BATCH * NEXP];        // softmax p(expert0) at token n<8
__device__ float    g_h1[BATCH * 2 * 9 * HID];    // expert-0 fc1 at (h in {0,1}, w in [0,9))

// ------------------------------------------------------------------
// K1: fused gate and fc1 (read-only; no out traffic)
// ------------------------------------------------------------------
__global__ void __launch_bounds__(128) gate_fc1_kernel(
    const float* __restrict__ x, const float* __restrict__ wg,
    const float* __restrict__ bg, const float* __restrict__ W1,
    const float* __restrict__ B1)
{
    __shared__ float pool[6152];
    __shared__ unsigned warpor[4];

    const int tid = threadIdx.x;
    const int blk = blockIdx.x;

    if (blk < 512) {
        // ================= gate path =================
        float* wg_s = pool;                 // [DIM*NEXP]
        float* bg_s = pool + 1024;          // [NEXP]
        float* xsbuf[2] = { pool + 1032, pool + 1032 + 2560 };  // [128*20] each

        const int tok0 = blk * 128;
        const float* xb = x + (size_t)tok0 * DIM;

        for (int i = tid; i < DIM * NEXP; i += 128) wg_s[i] = wg[i];
        if (tid < NEXP) bg_s[tid] = bg[tid];

        const int st_t = tid >> 2, st_q = tid & 3;

#pragma unroll
        for (int k = 0; k < 4; k++)
            __pipeline_memcpy_async(
                xsbuf[0] + (st_t + 32 * k) * 20 + st_q * 4,
                xb + (size_t)(st_t + 32 * k) * DIM + st_q * 4, 16);
        __pipeline_commit();

        float acc[NEXP];
#pragma unroll
        for (int e = 0; e < NEXP; e++) acc[e] = 0.0f;

#pragma unroll
        for (int ch = 0; ch < 8; ch++) {
            if (ch < 7) {
                float* nb = xsbuf[(ch + 1) & 1];
#pragma unroll
                for (int k = 0; k < 4; k++)
                    __pipeline_memcpy_async(
                        nb + (st_t + 32 * k) * 20 + st_q * 4,
                        xb + (size_t)(st_t + 32 * k) * DIM + (ch + 1) * 16 + st_q * 4, 16);
                __pipeline_commit();
                __pipeline_wait_prior(1);
            } else {
                __pipeline_wait_prior(0);
            }
            __syncthreads();

            const float* buf = xsbuf[ch & 1];
#pragma unroll
            for (int d4 = 0; d4 < 4; d4++) {
                float4 xv = *(const float4*)(buf + tid * 20 + d4 * 4);
                float xarr[4] = {xv.x, xv.y, xv.z, xv.w};
#pragma unroll
                for (int jj = 0; jj < 4; jj++) {
                    int dd = ch * 16 + d4 * 4 + jj;
                    float4 w0 = *(const float4*)(wg_s + dd * 8);
                    float4 w1 = *(const float4*)(wg_s + dd * 8 + 4);
                    float xd = xarr[jj];
                    acc[0] += xd * w0.x; acc[1] += xd * w0.y;
                    acc[2] += xd * w0.z; acc[3] += xd * w0.w;
                    acc[4] += xd * w1.x; acc[5] += xd * w1.y;
                    acc[6] += xd * w1.z; acc[7] += xd * w1.w;
                }
            }
            __syncthreads();
        }

        // logits, first-max argmax (matches jnp.argmax), softmax p0 at n<8
        float l[NEXP];
#pragma unroll
        for (int e = 0; e < NEXP; e++) l[e] = acc[e] + bg_s[e];
        float m = l[0]; int am = 0;
#pragma unroll
        for (int e = 1; e < NEXP; e++) if (l[e] > m) { m = l[e]; am = e; }

        const int tok = tok0 + tid;
        const int b = tok >> 12;
        const int n = tok & (NTOK - 1);
        if (n < NEXP) {
            float s = 0.0f;
#pragma unroll
            for (int e = 0; e < NEXP; e++) s += expf(l[e] - m);
            g_prob0[b * NEXP + n] = expf(l[0] - m) / s;
        }

        unsigned wor = __reduce_or_sync(0xffffffffu, 1u << am);
        if ((tid & 31) == 0) warpor[tid >> 5] = wor;
        __syncthreads();
        if (tid == 0)
            g_bm[blk] = warpor[0] | warpor[1] | warpor[2] | warpor[3];
    } else {
        // ================= fc1 path =================
        float* xs = pool;                   // [18*DIM]
        const int bb = blk - 512;           // [0,128)
        const int b  = bb >> 3, cg = bb & 7;

        for (int i = tid; i < 18 * DIM; i += 128) {
            int p = i >> 7, d = i & (DIM - 1);
            int h = p / 9, w = p % 9;
            int nn = h * 64 + w;
            xs[p * DIM + d] = x[((size_t)b * NTOK + nn) * DIM + d];
        }
        __syncthreads();

        const int c  = cg * 64 + (tid & 63);
        const int t0 = tid >> 6;

        float acc9[9];
        float bv = B1[c];
#pragma unroll
        for (int k = 0; k < 9; k++) acc9[k] = bv;

        for (int d4 = 0; d4 < DIM / 4; d4++) {
            float4 xv[9];
#pragma unroll
            for (int k = 0; k < 9; k++)
                xv[k] = *(const float4*)(xs + (t0 + 2 * k) * DIM + d4 * 4);
#pragma unroll
            for (int j = 0; j < 4; j++) {
                float w = W1[(size_t)(d4 * 4 + j) * HID + c];
#pragma unroll
                for (int k = 0; k < 9; k++) {
                    float xd = ((const float*)&xv[k])[j];
                    acc9[k] += xd * w;
                }
            }
        }

#pragma unroll
        for (int k = 0; k < 9; k++) {
            int p = t0 + 2 * k;
            int h = p / 9, w = p % 9;
            g_h1[(((size_t)b * 2 + h) * 9 + w) * HID + c] = acc9[k];
        }
    }
}

// ------------------------------------------------------------------
// K2: compute blocks (2 rows each) + zero blocks.
// ------------------------------------------------------------------
__global__ void __launch_bounds__(512, 1) out_kernel(
    const float* __restrict__ Wd, const float* __restrict__ Bd,
    const float* __restrict__ W2, const float* __restrict__ B2,
    float* __restrict__ out)
{
    const int tid = threadIdx.x;
    const int blk = blockIdx.x;

    if (blk >= 64) {
        // ---------------- zero path: rows n in [8,4096) ----------------
        const float4 z = make_float4(0.f, 0.f, 0.f, 0.f);
        for (int idx = (blk - 64) * 512 + tid; idx < ZTOT_VEC; idx += ZTHREADS) {
            int r = idx >> 5;               // row index in [0, BATCH*ZROWS)
            int v = idx & 31;               // float4 within row
            int b = r / ZROWS;
            int nn = 8 + (r - b * ZROWS);
            *((float4*)out + (size_t)(b * NTOK + nn) * (OUTD / 4) + v) = z;
        }
        return;
    }

    // ---------------- compute path: 2 batches x 1 j ----------------
    const int bp = blk >> 3, j = blk & 7;   // batches 2bp, 2bp+1
    const int b0 = 2 * bp;

    __shared__ float gs[2 * HID];
    __shared__ float partial[2 * 16 * OUTD];   // 16 KB
    __shared__ unsigned mor[BATCH];

    // mask[b'] = OR over the 32 gate blocks of batch b' (tid = b'*32 + blk)
    {
        unsigned m = __reduce_or_sync(0xffffffffu, g_bm[tid]);
        if ((tid & 31) == 0) mor[tid >> 5] = m;
    }

    // depthwise conv at (h=0, w=j) + exact GELU, 1 channel/thread, 2 batches
    {
        const int c = tid;
#pragma unroll
        for (int r = 0; r < 2; r++) {
            float conv = Bd[c];
#pragma unroll
            for (int hh = 0; hh < 2; hh++) {
#pragma unroll
                for (int kw = 0; kw < 3; kw++) {
                    int wp = j + kw - 1;
                    if (wp >= 0 && wp <= 8) {
                        conv += g_h1[(((size_t)(b0 + r) * 2 + hh) * 9 + wp) * HID + c]
                              * Wd[((hh + 1) * 3 + kw) * HID + c];
                    }
                }
            }
            gs[r * HID + c] = 0.5f * conv * (1.0f + erff(conv * 0.70710678118654752f));
        }
    }
    __syncthreads();

    // fc2 partials: warp s covers c in [32s,32s+32); thread t -> outputs 4t..4t+3
    {
        const int s = tid >> 5, t = tid & 31;
        const float* w2p = W2 + (size_t)(s * 32) * OUTD + 4 * t;
        const float* g0 = gs + s * 32;
        const float* g1 = gs + HID + s * 32;
        float4 a0 = make_float4(0.f, 0.f, 0.f, 0.f);
        float4 a1 = make_float4(0.f, 0.f, 0.f, 0.f);
#pragma unroll
        for (int i = 0; i < 32; i++) {
            float4 w = *(const float4*)(w2p + (size_t)i * OUTD);
            float u = g0[i], v = g1[i];
            a0.x += u * w.x; a0.y += u * w.y; a0.z += u * w.z; a0.w += u * w.w;
            a1.x += v * w.x; a1.y += v * w.y; a1.z += v * w.z; a1.w += v * w.w;
        }
        *(float4*)(partial + s * OUTD + 4 * t) = a0;
        *(float4*)(partial + 16 * OUTD + s * OUTD + 4 * t) = a1;
    }
    __syncthreads();

    // reduce + gate + store: 256 active threads, one (row, output) each
    if (tid < 256) {
        const int r = tid >> 7, o = tid & (OUTD - 1);
        const int b = b0 + r;

        float s = 0.0f;
#pragma unroll
        for (int bb = 0; bb < BATCH; bb++)
            s += g_prob0[bb * NEXP + j] * (float)((mor[bb] >> j) & 1u);
        float gv = g_prob0[b * NEXP + j] * (float)((mor[b] >> j) & 1u);
        float gate_s = gv / (s + EPS) * (float)BATCH;   // capacity = 16.0

        float acc = B2[o];
        const float* pp = partial + r * 16 * OUTD + o;
#pragma unroll
        for (int sl = 0; sl < 16; sl++) acc += pp[sl * OUTD];

        out[((size_t)b * NTOK + j) * OUTD + o] = gate_s * acc;
    }
}

// ------------------------------------------------------------------
extern "C" void kernel_launch(void* const* d_in, const int* in_sizes, int n_in,
                              void* d_out, int out_size)
{
    // input order: x, [H, W,] wg, bg, W1, B1, Wd, Bd, W2, B2
    int o = (n_in >= 11) ? 3 : 1;
    const float* x  = (const float*)d_in[0];
    const float* wg = (const float*)d_in[o + 0];
    const float* bg = (const float*)d_in[o + 1];
    const float* W1 = (const float*)d_in[o + 2];
    const float* B1 = (const float*)d_in[o + 3];
    const float* Wd = (const float*)d_in[o + 4];
    const float* Bd = (const float*)d_in[o + 5];
    const float* W2 = (const float*)d_in[o + 6];
    const float* B2 = (const float*)d_in[o + 7];
    float* out = (float*)d_out;

    gate_fc1_kernel<<<640, 128>>>(x, wg, bg, W1, B1);
    out_kernel<<<448, 512>>>(Wd, Bd, W2, B2, out);
}

// round 10
// speedup vs baseline: 1.7778x; 1.2305x over previous
#include <cuda_runtime.h>
#include <cuda_bf16.h>
#include <cuda_pipeline.h>
#include <math.h>

// SwitchMoE with the reference's dim-1 scatter gate bug:
//   mask[b, top1[b,n], 0] = 1  =>  output nonzero only for n<8, expert 0.
// E=8, DIM=128, HID=512, OUT=128, B=16, H=W=64, N=4096.
//
// 2 launches:
//   K1 (grid 640 x 128thr): blocks <512 = warp-autonomous gate
//       (4-stage cp.async ring per warp, __syncwarp only) + out zeroing;
//       blocks >=512 = expert-0 fc1 at the 18 needed pixels/batch.
//   K2 (grid 64 x 512thr, 1 wave): dwconv+GELU+fc2+gate, 2 rows/block.

#define BATCH 16
#define NTOK  4096
#define DIM   128
#define NEXP  8
#define HID   512
#define OUTD  128
#define EPS   1e-6f

// ---- scratch (device globals; every element rewritten each call) ----
__device__ unsigned g_bm[512];                    // per-gate-block OR of (1<<argmax)
__device__ float    g_prob0[BATCH * NEXP];        // softmax p(expert0) at token n<8
__device__ float    g_h1[BATCH * 2 * 9 * HID];    // expert-0 fc1 at (h in {0,1}, w in [0,9))

// ------------------------------------------------------------------
// K1: warp-autonomous gate (+ out zeroing) and fc1
// ------------------------------------------------------------------
__global__ void __launch_bounds__(128, 5) gate_fc1_kernel(
    const float* __restrict__ x, const float* __restrict__ wg,
    const float* __restrict__ bg, const float* __restrict__ W1,
    const float* __restrict__ B1, float* __restrict__ out)
{
    // pool aliasing:
    //   gate: wg_s[1024] | bg_s[8] | xs[4 warps][4 stages][32*20] = 11272 floats
    //   fc1 : xs18[18*128] = 2304 floats
    __shared__ float pool[11272];
    __shared__ unsigned warpor[4];

    const int tid = threadIdx.x;
    const int blk = blockIdx.x;

    if (blk < 512) {
        // ================= gate path =================
        float* wg_s = pool;                          // [DIM*NEXP]
        float* bg_s = pool + 1024;                   // [NEXP]
        const int wid = tid >> 5, lane = tid & 31;
        float* xw = pool + 1032 + wid * (4 * 640);   // this warp's 4-stage ring

        const int tok0 = blk * 128;
        const float* xb = x + (size_t)(tok0 + wid * 32) * DIM;  // warp's 32 tokens

        for (int i = tid; i < DIM * NEXP; i += 128) wg_s[i] = wg[i];
        if (tid < NEXP) bg_s[tid] = bg[tid];
        __syncthreads();                             // wg_s ready; warps go autonomous

        // staging coords: lane copies quarter q of tokens tq, tq+8, tq+16, tq+24
        const int tq = lane >> 2, q = lane & 3;

        // prologue: stage chunks 0..2 (each chunk = 32 tokens x 16 dims)
#pragma unroll
        for (int ch = 0; ch < 3; ch++) {
            float* dst = xw + ch * 640;
#pragma unroll
            for (int k = 0; k < 4; k++) {
                int t = tq + 8 * k;
                __pipeline_memcpy_async(dst + t * 20 + q * 4,
                    xb + (size_t)t * DIM + ch * 16 + q * 4, 16);
            }
            __pipeline_commit();
        }

        float acc[NEXP];
#pragma unroll
        for (int e = 0; e < NEXP; e++) acc[e] = 0.0f;

#pragma unroll
        for (int ch = 0; ch < 8; ch++) {
            if (ch < 5) {                            // stage chunk ch+3
                float* dst = xw + ((ch + 3) & 3) * 640;
#pragma unroll
                for (int k = 0; k < 4; k++) {
                    int t = tq + 8 * k;
                    __pipeline_memcpy_async(dst + t * 20 + q * 4,
                        xb + (size_t)t * DIM + (ch + 3) * 16 + q * 4, 16);
                }
                __pipeline_commit();
                __pipeline_wait_prior(3);            // chunk ch landed
            } else {
                __pipeline_wait_prior(7 - ch);
            }
            __syncwarp();

            const float* buf = xw + (ch & 3) * 640;
#pragma unroll
            for (int d4 = 0; d4 < 4; d4++) {
                float4 xv = *(const float4*)(buf + lane * 20 + d4 * 4);
                float xarr[4] = {xv.x, xv.y, xv.z, xv.w};
#pragma unroll
                for (int jj = 0; jj < 4; jj++) {
                    int dd = ch * 16 + d4 * 4 + jj;
                    float4 w0 = *(const float4*)(wg_s + dd * 8);
                    float4 w1 = *(const float4*)(wg_s + dd * 8 + 4);
                    float xd = xarr[jj];
                    acc[0] += xd * w0.x; acc[1] += xd * w0.y;
                    acc[2] += xd * w0.z; acc[3] += xd * w0.w;
                    acc[4] += xd * w1.x; acc[5] += xd * w1.y;
                    acc[6] += xd * w1.z; acc[7] += xd * w1.w;
                }
            }
            __syncwarp();                            // done reading buf before re-fill
        }

        // logits, first-max argmax (matches jnp.argmax), softmax p0 at n<8
        float l[NEXP];
#pragma unroll
        for (int e = 0; e < NEXP; e++) l[e] = acc[e] + bg_s[e];
        float m = l[0]; int am = 0;
#pragma unroll
        for (int e = 1; e < NEXP; e++) if (l[e] > m) { m = l[e]; am = e; }

        const int tok = tok0 + tid;                  // wid*32+lane == tid
        const int b = tok >> 12;
        const int n = tok & (NTOK - 1);
        if (n < NEXP) {
            float s = 0.0f;
#pragma unroll
            for (int e = 0; e < NEXP; e++) s += expf(l[e] - m);
            g_prob0[b * NEXP + n] = expf(l[0] - m) / s;
        }

        // per-block argmax bitmask (replay-safe: every slot rewritten each call)
        unsigned wor = __reduce_or_sync(0xffffffffu, 1u << am);
        if (lane == 0) warpor[wid] = wor;
        __syncthreads();
        if (tid == 0)
            g_bm[blk] = warpor[0] | warpor[1] | warpor[2] | warpor[3];

        // zero this block's 128 output rows (contiguous 64KB; free vs stalls)
        float4 z = make_float4(0.f, 0.f, 0.f, 0.f);
        float4* ob = (float4*)(out + (size_t)tok0 * OUTD);
#pragma unroll 8
        for (int i = tid; i < 128 * (OUTD / 4); i += 128) ob[i] = z;
    } else {
        // ================= fc1 path =================
        // expert-0 fc1 at 18 pixels/batch: h in {0,1}, w in [0,9)
        float* xs = pool;                            // [18*DIM]
        const int bb = blk - 512;                    // [0,128)
        const int b  = bb >> 3, cg = bb & 7;

        for (int i = tid; i < 18 * DIM; i += 128) {
            int p = i >> 7, d = i & (DIM - 1);
            int h = p / 9, w = p % 9;
            int nn = h * 64 + w;
            xs[p * DIM + d] = x[((size_t)b * NTOK + nn) * DIM + d];
        }
        __syncthreads();

        const int c  = cg * 64 + (tid & 63);
        const int t0 = tid >> 6;                     // tokens t0, t0+2, ..., t0+16

        float acc9[9];
        float bv = B1[c];
#pragma unroll
        for (int k = 0; k < 9; k++) acc9[k] = bv;

        for (int d4 = 0; d4 < DIM / 4; d4++) {
            float4 xv[9];
#pragma unroll
            for (int k = 0; k < 9; k++)
                xv[k] = *(const float4*)(xs + (t0 + 2 * k) * DIM + d4 * 4);
#pragma unroll
            for (int j = 0; j < 4; j++) {
                float w = W1[(size_t)(d4 * 4 + j) * HID + c];
#pragma unroll
                for (int k = 0; k < 9; k++) {
                    float xd = ((const float*)&xv[k])[j];
                    acc9[k] += xd * w;
                }
            }
        }

#pragma unroll
        for (int k = 0; k < 9; k++) {
            int p = t0 + 2 * k;
            int h = p / 9, w = p % 9;
            g_h1[(((size_t)b * 2 + h) * 9 + w) * HID + c] = acc9[k];
        }
    }
}

// ------------------------------------------------------------------
// K2: dwconv(3x3, SAME) + bias + exact GELU + fc2 + gate; 64 blocks
// (2 batches x 1 j each) = 1 wave. Writes the 128 rows with n<8.
// ------------------------------------------------------------------
__global__ void __launch_bounds__(512, 1) out_kernel(
    const float* __restrict__ Wd, const float* __restrict__ Bd,
    const float* __restrict__ W2, const float* __restrict__ B2,
    float* __restrict__ out)
{
    const int tid = threadIdx.x;
    const int blk = blockIdx.x;
    const int bp = blk >> 3, j = blk & 7;            // batches 2bp, 2bp+1
    const int b0 = 2 * bp;

    __shared__ float gs[2 * HID];
    __shared__ float partial[2 * 16 * OUTD];         // 16 KB
    __shared__ unsigned mor[BATCH];

    // mask[b'] = OR over the 32 gate blocks of batch b' (tid = b'*32 + blk)
    {
        unsigned m = __reduce_or_sync(0xffffffffu, g_bm[tid]);
        if ((tid & 31) == 0) mor[tid >> 5] = m;
    }

    // depthwise conv at (h=0, w=j) + exact GELU, 1 channel/thread, 2 batches
    {
        const int c = tid;
#pragma unroll
        for (int r = 0; r < 2; r++) {
            float conv = Bd[c];
#pragma unroll
            for (int hh = 0; hh < 2; hh++) {
#pragma unroll
                for (int kw = 0; kw < 3; kw++) {
                    int wp = j + kw - 1;
                    if (wp >= 0 && wp <= 8) {
                        conv += g_h1[(((size_t)(b0 + r) * 2 + hh) * 9 + wp) * HID + c]
                              * Wd[((hh + 1) * 3 + kw) * HID + c];
                    }
                }
            }
            gs[r * HID + c] = 0.5f * conv * (1.0f + erff(conv * 0.70710678118654752f));
        }
    }
    __syncthreads();

    // fc2 partials: warp s covers c in [32s,32s+32); thread t -> outputs 4t..4t+3
    {
        const int s = tid >> 5, t = tid & 31;
        const float* w2p = W2 + (size_t)(s * 32) * OUTD + 4 * t;
        const float* g0 = gs + s * 32;
        const float* g1 = gs + HID + s * 32;
        float4 a0 = make_float4(0.f, 0.f, 0.f, 0.f);
        float4 a1 = make_float4(0.f, 0.f, 0.f, 0.f);
#pragma unroll
        for (int i = 0; i < 32; i++) {
            float4 w = *(const float4*)(w2p + (size_t)i * OUTD);
            float u = g0[i], v = g1[i];
            a0.x += u * w.x; a0.y += u * w.y; a0.z += u * w.z; a0.w += u * w.w;
            a1.x += v * w.x; a1.y += v * w.y; a1.z += v * w.z; a1.w += v * w.w;
        }
        *(float4*)(partial + s * OUTD + 4 * t) = a0;
        *(float4*)(partial + 16 * OUTD + s * OUTD + 4 * t) = a1;
    }
    __syncthreads();

    // reduce + gate + store: 256 active threads, one (row, output) each
    if (tid < 256) {
        const int r = tid >> 7, o = tid & (OUTD - 1);
        const int b = b0 + r;

        float s = 0.0f;
#pragma unroll
        for (int bb = 0; bb < BATCH; bb++)
            s += g_prob0[bb * NEXP + j] * (float)((mor[bb] >> j) & 1u);
        float gv = g_prob0[b * NEXP + j] * (float)((mor[b] >> j) & 1u);
        float gate_s = gv / (s + EPS) * (float)BATCH;   // capacity = 16.0

        float acc = B2[o];
        const float* pp = partial + r * 16 * OUTD + o;
#pragma unroll
        for (int sl = 0; sl < 16; sl++) acc += pp[sl * OUTD];

        out[((size_t)b * NTOK + j) * OUTD + o] = gate_s * acc;
    }
}

// ------------------------------------------------------------------
extern "C" void kernel_launch(void* const* d_in, const int* in_sizes, int n_in,
                              void* d_out, int out_size)
{
    // input order: x, [H, W,] wg, bg, W1, B1, Wd, Bd, W2, B2
    int o = (n_in >= 11) ? 3 : 1;
    const float* x  = (const float*)d_in[0];
    const float* wg = (const float*)d_in[o + 0];
    const float* bg = (const float*)d_in[o + 1];
    const float* W1 = (const float*)d_in[o + 2];
    const float* B1 = (const float*)d_in[o + 3];
    const float* Wd = (const float*)d_in[o + 4];
    const float* Bd = (const float*)d_in[o + 5];
    const float* W2 = (const float*)d_in[o + 6];
    const float* B2 = (const float*)d_in[o + 7];
    float* out = (float*)d_out;

    gate_fc1_kernel<<<640, 128>>>(x, wg, bg, W1, B1, out);
    out_kernel<<<64, 512>>>(Wd, Bd, W2, B2, out);
}

// round 12
// speedup vs baseline: 1.7827x; 1.0028x over previous
#include <cuda_runtime.h>
#include <cuda_bf16.h>
#include <cuda_pipeline.h>
#include <math.h>

// SwitchMoE with the reference's dim-1 scatter gate bug:
//   mask[b, top1[b,n], 0] = 1  =>  output nonzero only for n<8, expert 0.
// E=8, DIM=128, HID=512, OUT=128, B=16, H=W=64, N=4096.
//
// 2 launches:
//   K1 (grid 640 x 128thr): blocks <512 = warp-autonomous gate (4-stage
//       cp.async ring, FFMA2 packed accumulators) + interleaved out zeroing
//       + late L2 prefetch of W2/Wd/B2; blocks >=512 = expert-0 fc1.
//   K2 (grid 128 x 512thr, 1 block/SM, 1 wave): dwconv+GELU+fc2+gate, 1 row/block.

#define BATCH 16
#define NTOK  4096
#define DIM   128
#define NEXP  8
#define HID   512
#define OUTD  128
#define EPS   1e-6f

// ---- scratch (device globals; every element rewritten each call) ----
__device__ unsigned g_bm[512];                    // per-gate-block OR of (1<<argmax)
__device__ float    g_prob0[BATCH * NEXP];        // softmax p(expert0) at token n<8
__device__ float    g_h1[BATCH * 2 * 9 * HID];    // expert-0 fc1 at (h in {0,1}, w in [0,9))

#define FMA2(acc, a, b) \
    asm("fma.rn.f32x2 %0, %1, %2, %0;" : "+l"(acc) : "l"(a), "l"(b))

// ------------------------------------------------------------------
// K1: warp-autonomous gate (+ interleaved out zeroing + L2 prefetch) and fc1
// ------------------------------------------------------------------
__global__ void __launch_bounds__(128, 5) gate_fc1_kernel(
    const float* __restrict__ x, const float* __restrict__ wg,
    const float* __restrict__ bg, const float* __restrict__ W1,
    const float* __restrict__ B1, const float* __restrict__ Wd,
    const float* __restrict__ W2, const float* __restrict__ B2,
    float* __restrict__ out)
{
    // pool aliasing:
    //   gate: wg_s[1024] | bg_s[8] | xs[4 warps][4 stages][32*20] = 11272 floats
    //   fc1 : xs18[18*128] = 2304 floats
    __shared__ float pool[11272];
    __shared__ unsigned warpor[4];

    const int tid = threadIdx.x;
    const int blk = blockIdx.x;

    if (blk < 512) {
        // ================= gate path =================
        float* wg_s = pool;                          // [DIM*NEXP]
        float* bg_s = pool + 1024;                   // [NEXP]
        const int wid = tid >> 5, lane = tid & 31;
        float* xw = pool + 1032 + wid * (4 * 640);   // this warp's 4-stage ring

        const int tok0 = blk * 128;
        const float* xb = x + (size_t)(tok0 + wid * 32) * DIM;  // warp's 32 tokens
        float4* ob = (float4*)(out + (size_t)tok0 * OUTD);      // block's 128 out rows

        for (int i = tid; i < DIM * NEXP; i += 128) wg_s[i] = wg[i];
        if (tid < NEXP) bg_s[tid] = bg[tid];
        __syncthreads();                             // wg_s ready; warps go autonomous

        // staging coords: lane copies quarter q of tokens tq, tq+8, tq+16, tq+24
        const int tq = lane >> 2, q = lane & 3;

        // prologue: stage chunks 0..2 (each chunk = 32 tokens x 16 dims)
#pragma unroll
        for (int ch = 0; ch < 3; ch++) {
            float* dst = xw + ch * 640;
#pragma unroll
            for (int k = 0; k < 4; k++) {
                int t = tq + 8 * k;
                __pipeline_memcpy_async(dst + t * 20 + q * 4,
                    xb + (size_t)t * DIM + ch * 16 + q * 4, 16);
            }
            __pipeline_commit();
        }

        // packed accumulators: (e0,e1) (e2,e3) (e4,e5) (e6,e7)
        unsigned long long a01 = 0ull, a23 = 0ull, a45 = 0ull, a67 = 0ull;
        const float4 z4 = make_float4(0.f, 0.f, 0.f, 0.f);

#pragma unroll
        for (int ch = 0; ch < 8; ch++) {
            if (ch < 5) {                            // stage chunk ch+3
                float* dst = xw + ((ch + 3) & 3) * 640;
#pragma unroll
                for (int k = 0; k < 4; k++) {
                    int t = tq + 8 * k;
                    __pipeline_memcpy_async(dst + t * 20 + q * 4,
                        xb + (size_t)t * DIM + (ch + 3) * 16 + q * 4, 16);
                }
                __pipeline_commit();
                __pipeline_wait_prior(3);            // chunk ch landed
            } else {
                __pipeline_wait_prior(7 - ch);
            }
            __syncwarp();

            const float* buf = xw + (ch & 3) * 640;
#pragma unroll
            for (int d4 = 0; d4 < 4; d4++) {
                float4 xv = *(const float4*)(buf + lane * 20 + d4 * 4);
                float xarr[4] = {xv.x, xv.y, xv.z, xv.w};
#pragma unroll
                for (int jj = 0; jj < 4; jj++) {
                    int dd = ch * 16 + d4 * 4 + jj;
                    const ulonglong2* wrow = (const ulonglong2*)(wg_s + dd * 8);
                    ulonglong2 wa = wrow[0];
                    ulonglong2 wb = wrow[1];
                    unsigned long long xd2;
                    asm("mov.b64 %0, {%1, %1};" : "=l"(xd2) : "f"(xarr[jj]));
                    FMA2(a01, xd2, wa.x);
                    FMA2(a23, xd2, wa.y);
                    FMA2(a45, xd2, wb.x);
                    FMA2(a67, xd2, wb.y);
                }
            }
            __syncwarp();                            // done reading buf before re-fill

            // interleaved zero-stores: 4 float4 rows-chunk per thread per chunk
#pragma unroll
            for (int k = 0; k < 4; k++)
                ob[ch * 512 + k * 128 + tid] = z4;
        }

        // unpack logits, add bias; first-max argmax (matches jnp.argmax)
        float l[NEXP];
        asm("mov.b64 {%0, %1}, %2;" : "=f"(l[0]), "=f"(l[1]) : "l"(a01));
        asm("mov.b64 {%0, %1}, %2;" : "=f"(l[2]), "=f"(l[3]) : "l"(a23));
        asm("mov.b64 {%0, %1}, %2;" : "=f"(l[4]), "=f"(l[5]) : "l"(a45));
        asm("mov.b64 {%0, %1}, %2;" : "=f"(l[6]), "=f"(l[7]) : "l"(a67));
#pragma unroll
        for (int e = 0; e < NEXP; e++) l[e] += bg_s[e];
        float m = l[0]; int am = 0;
#pragma unroll
        for (int e = 1; e < NEXP; e++) if (l[e] > m) { m = l[e]; am = e; }

        const int tok = tok0 + tid;                  // wid*32+lane == tid
        const int b = tok >> 12;
        const int n = tok & (NTOK - 1);
        if (n < NEXP) {
            float s = 0.0f;
#pragma unroll
            for (int e = 0; e < NEXP; e++) s += expf(l[e] - m);
            g_prob0[b * NEXP + n] = expf(l[0] - m) / s;
        }

        // per-block argmax bitmask (replay-safe: every slot rewritten each call)
        unsigned wor = __reduce_or_sync(0xffffffffu, 1u << am);
        if (lane == 0) warpor[wid] = wor;
        __syncthreads();
        if (tid == 0)
            g_bm[blk] = warpor[0] | warpor[1] | warpor[2] | warpor[3];

        // late L2 prefetch of K2's weights (4 W2 lines per block -> all 2048;
        // first 144 blocks: 1 Wd line; first 4 blocks: 1 B2 line)
        if (tid < 4) {
            const float* p = W2 + ((size_t)blk * 4 + tid) * 32;
            asm volatile("prefetch.global.L2 [%0];" :: "l"(p));
        }
        if (blk < 144 && tid == 8) {
            const float* p = Wd + (size_t)blk * 32;
            asm volatile("prefetch.global.L2 [%0];" :: "l"(p));
        }
        if (blk < 4 && tid == 9) {
            const float* p = B2 + (size_t)blk * 32;
            asm volatile("prefetch.global.L2 [%0];" :: "l"(p));
        }
    } else {
        // ================= fc1 path =================
        // expert-0 fc1 at 18 pixels/batch: h in {0,1}, w in [0,9)
        float* xs = pool;                            // [18*DIM]
        const int bb = blk - 512;                    // [0,128)
        const int b  = bb >> 3, cg = bb & 7;

        for (int i = tid; i < 18 * DIM; i += 128) {
            int p = i >> 7, d = i & (DIM - 1);
            int h = p / 9, w = p % 9;
            int nn = h * 64 + w;
            xs[p * DIM + d] = x[((size_t)b * NTOK + nn) * DIM + d];
        }
        __syncthreads();

        const int c  = cg * 64 + (tid & 63);
        const int t0 = tid >> 6;                     // tokens t0, t0+2, ..., t0+16

        float acc9[9];
        float bv = B1[c];
#pragma unroll
        for (int k = 0; k < 9; k++) acc9[k] = bv;

        for (int d4 = 0; d4 < DIM / 4; d4++) {
            float4 xv[9];
#pragma unroll
            for (int k = 0; k < 9; k++)
                xv[k] = *(const float4*)(xs + (t0 + 2 * k) * DIM + d4 * 4);
#pragma unroll
            for (int j = 0; j < 4; j++) {
                float w = W1[(size_t)(d4 * 4 + j) * HID + c];
#pragma unroll
                for (int k = 0; k < 9; k++) {
                    float xd = ((const float*)&xv[k])[j];
                    acc9[k] += xd * w;
                }
            }
        }

#pragma unroll
        for (int k = 0; k < 9; k++) {
            int p = t0 + 2 * k;
            int h = p / 9, w = p % 9;
            g_h1[(((size_t)b * 2 + h) * 9 + w) * HID + c] = acc9[k];
        }
    }
}

// ------------------------------------------------------------------
// K2: dwconv(3x3, SAME) + bias + exact GELU + fc2 + gate; 128 blocks,
// 1 row (b,j) each, 1 block/SM, single wave.
// ------------------------------------------------------------------
__global__ void __launch_bounds__(512, 1) out_kernel(
    const float* __restrict__ Wd, const float* __restrict__ Bd,
    const float* __restrict__ W2, const float* __restrict__ B2,
    float* __restrict__ out)
{
    const int tid = threadIdx.x;
    const int blk = blockIdx.x;
    const int b = blk >> 3, j = blk & 7;

    __shared__ float gs[HID];
    __shared__ float partial[16 * OUTD];             // 8 KB
    __shared__ unsigned mor[BATCH];

    // mask[b'] = OR over the 32 gate blocks of batch b' (tid = b'*32 + blk)
    {
        unsigned m = __reduce_or_sync(0xffffffffu, g_bm[tid]);
        if ((tid & 31) == 0) mor[tid >> 5] = m;
    }

    // depthwise conv at (h=0, w=j) + exact GELU, 1 channel/thread
    {
        const int c = tid;
        float conv = Bd[c];
#pragma unroll
        for (int hh = 0; hh < 2; hh++) {
#pragma unroll
            for (int kw = 0; kw < 3; kw++) {
                int wp = j + kw - 1;
                if (wp >= 0 && wp <= 8) {
                    conv += g_h1[(((size_t)b * 2 + hh) * 9 + wp) * HID + c]
                          * Wd[((hh + 1) * 3 + kw) * HID + c];
                }
            }
        }
        gs[c] = 0.5f * conv * (1.0f + erff(conv * 0.70710678118654752f));
    }
    __syncthreads();

    // fc2 partials: warp s covers c in [32s,32s+32); thread t -> outputs 4t..4t+3
    {
        const int s = tid >> 5, t = tid & 31;
        const float* w2p = W2 + (size_t)(s * 32) * OUTD + 4 * t;
        const float* gp  = gs + s * 32;
        float4 a = make_float4(0.f, 0.f, 0.f, 0.f);
#pragma unroll
        for (int i = 0; i < 32; i++) {
            float g = gp[i];
            float4 w = *(const float4*)(w2p + (size_t)i * OUTD);
            a.x += g * w.x; a.y += g * w.y; a.z += g * w.z; a.w += g * w.w;
        }
        *(float4*)(partial + s * OUTD + 4 * t) = a;
    }
    __syncthreads();

    // reduce + gate + store: 128 active threads, one output each
    if (tid < OUTD) {
        float s = 0.0f;
#pragma unroll
        for (int bb = 0; bb < BATCH; bb++)
            s += g_prob0[bb * NEXP + j] * (float)((mor[bb] >> j) & 1u);
        float gv = g_prob0[b * NEXP + j] * (float)((mor[b] >> j) & 1u);
        float gate_s = gv / (s + EPS) * (float)BATCH;   // capacity = 16.0

        float acc = B2[tid];
#pragma unroll
        for (int sl = 0; sl < 16; sl++) acc += partial[sl * OUTD + tid];

        out[((size_t)b * NTOK + j) * OUTD + tid] = gate_s * acc;
    }
}

// ------------------------------------------------------------------
extern "C" void kernel_launch(void* const* d_in, const int* in_sizes, int n_in,
                              void* d_out, int out_size)
{
    // input order: x, [H, W,] wg, bg, W1, B1, Wd, Bd, W2, B2
    int o = (n_in >= 11) ? 3 : 1;
    const float* x  = (const float*)d_in[0];
    const float* wg = (const float*)d_in[o + 0];
    const float* bg = (const float*)d_in[o + 1];
    const float* W1 = (const float*)d_in[o + 2];
    const float* B1 = (const float*)d_in[o + 3];
    const float* Wd = (const float*)d_in[o + 4];
    const float* Bd = (const float*)d_in[o + 5];
    const float* W2 = (const float*)d_in[o + 6];
    const float* B2 = (const float*)d_in[o + 7];
    float* out = (float*)d_out;

    gate_fc1_kernel<<<640, 128>>>(x, wg, bg, W1, B1, Wd, W2, B2, out);
    out_kernel<<<128, 512>>>(Wd, Bd, W2, B2, out);
}